// round 16
// baseline (speedup 1.0000x reference)
#include <cuda_runtime.h>

// ---------------- problem constants ----------------
#define BB   16
#define TT   1024
#define CDIM 768
#define C3   2304      // 3*C
#define HID  3072      // 4*C
#define BT   16384     // B*T
#define NHEAD 12
#define HD   64

// ---------------- device scratch (sanctioned __device__ globals) ----------------
__device__ float g_ln  [(size_t)BT * CDIM];   // ln1 out, then reused as h2
__device__ float g_qkv [(size_t)BT * C3];     // qkv
__device__ float g_y   [(size_t)BT * CDIM];   // attention out
__device__ float g_hid1[(size_t)BT * HID];
__device__ float g_hid2[(size_t)BT * HID];
__device__ float g_gates[(size_t)BT * 2];     // normalized combine gates
__device__ float g_aux [64];                  // [0..31]=gsum[b][e], [32..63]=cnt[b][e]

// ---------------- fused LayerNorm: one block per row ----------------
__global__ __launch_bounds__(256) void ln_k(const float* __restrict__ x,
                                            const float* __restrict__ w,
                                            const float* __restrict__ b,
                                            float* __restrict__ out)
{
    __shared__ float sx[CDIM];
    __shared__ float red[8];
    __shared__ float stat[2];
    int row = blockIdx.x, tid = threadIdx.x;
    const float* xp = x + (size_t)row * CDIM;

    float s = 0.f;
    for (int i = tid; i < CDIM; i += 256) { float v = xp[i]; sx[i] = v; s += v; }
    #pragma unroll
    for (int o = 16; o; o >>= 1) s += __shfl_down_sync(0xffffffffu, s, o);
    if ((tid & 31) == 0) red[tid >> 5] = s;
    __syncthreads();
    if (tid == 0) {
        float t = 0.f;
        #pragma unroll
        for (int i = 0; i < 8; i++) t += red[i];
        stat[0] = t / (float)CDIM;
    }
    __syncthreads();
    float m = stat[0];
    float s2 = 0.f;
    for (int i = tid; i < CDIM; i += 256) { float d = sx[i] - m; s2 += d * d; }
    #pragma unroll
    for (int o = 16; o; o >>= 1) s2 += __shfl_down_sync(0xffffffffu, s2, o);
    if ((tid & 31) == 0) red[tid >> 5] = s2;
    __syncthreads();
    if (tid == 0) {
        float t = 0.f;
        #pragma unroll
        for (int i = 0; i < 8; i++) t += red[i];
        stat[1] = rsqrtf(t / (float)CDIM + 1e-5f);
    }
    __syncthreads();
    float r = stat[1];
    float* op = out + (size_t)row * CDIM;
    for (int i = tid; i < CDIM; i += 256) op[i] = (sx[i] - m) * r * w[i] + b[i];
}

// ---------------- tiled fp32 SGEMM, 128x128 block tile, BK=8, 8x8/thread ----------------
// EPI: 0 = C = acc + bias[n]
//      1 = C = acc + bias[n] + extra[row*N+n]     (residual write)
//      2 = C = leaky_relu(acc)
//      3 = C += extra[row*2+gsel] * acc           (gated MoE accumulate)
template<int EPI>
__global__ __launch_bounds__(256) void sgemm_k(const float* __restrict__ A,
                                               const float* __restrict__ Bm,
                                               float* __restrict__ C,
                                               const float* __restrict__ bias,
                                               const float* __restrict__ extra,
                                               int M, int N, int K, int gsel)
{
    __shared__ float As[8][132];   // +4 pad kills STS bank conflicts
    __shared__ float Bs[8][128];

    int tid = threadIdx.x;
    int bx = blockIdx.x, by = blockIdx.y;
    int tx = tid & 15, ty = tid >> 4;

    int arow = tid >> 1;
    int ak4  = (tid & 1) * 4;
    const float* Aptr = A + (size_t)(by * 128 + arow) * K + ak4;

    int brow = tid >> 5;
    int bcol = (tid & 31) * 4;
    const float* Bptr = Bm + (size_t)brow * N + bx * 128 + bcol;

    float acc[8][8] = {};
    float4 a4 = *(const float4*)Aptr;
    float4 b4 = *(const float4*)Bptr;

    int ntile = K >> 3;
    for (int kt = 0; kt < ntile; kt++) {
        __syncthreads();
        As[ak4 + 0][arow] = a4.x;
        As[ak4 + 1][arow] = a4.y;
        As[ak4 + 2][arow] = a4.z;
        As[ak4 + 3][arow] = a4.w;
        *(float4*)&Bs[brow][bcol] = b4;
        __syncthreads();
        if (kt + 1 < ntile) {
            a4 = *(const float4*)(Aptr + (size_t)(kt + 1) * 8);
            b4 = *(const float4*)(Bptr + (size_t)(kt + 1) * 8 * N);
        }
        #pragma unroll
        for (int k = 0; k < 8; k++) {
            float af[8], bf[8];
            *(float4*)&af[0] = *(const float4*)&As[k][ty * 4];
            *(float4*)&af[4] = *(const float4*)&As[k][ty * 4 + 64];
            *(float4*)&bf[0] = *(const float4*)&Bs[k][tx * 4];
            *(float4*)&bf[4] = *(const float4*)&Bs[k][tx * 4 + 64];
            #pragma unroll
            for (int i = 0; i < 8; i++)
                #pragma unroll
                for (int j = 0; j < 8; j++)
                    acc[i][j] += af[i] * bf[j];
        }
    }

    #pragma unroll
    for (int i = 0; i < 8; i++) {
        int row = by * 128 + ty * 4 + (i & 3) + (i >> 2) * 64;
        #pragma unroll
        for (int jh = 0; jh < 2; jh++) {
            int col = bx * 128 + tx * 4 + jh * 64;
            size_t off = (size_t)row * N + col;
            float4 v;
            v.x = acc[i][jh * 4 + 0];
            v.y = acc[i][jh * 4 + 1];
            v.z = acc[i][jh * 4 + 2];
            v.w = acc[i][jh * 4 + 3];
            if (EPI == 0) {
                v.x += bias[col]; v.y += bias[col + 1]; v.z += bias[col + 2]; v.w += bias[col + 3];
                *(float4*)&C[off] = v;
            } else if (EPI == 1) {
                float4 r = *(const float4*)&extra[off];
                v.x += bias[col]     + r.x;
                v.y += bias[col + 1] + r.y;
                v.z += bias[col + 2] + r.z;
                v.w += bias[col + 3] + r.w;
                *(float4*)&C[off] = v;
            } else if (EPI == 2) {
                v.x = v.x >= 0.f ? v.x : 0.01f * v.x;
                v.y = v.y >= 0.f ? v.y : 0.01f * v.y;
                v.z = v.z >= 0.f ? v.z : 0.01f * v.z;
                v.w = v.w >= 0.f ? v.w : 0.01f * v.w;
                *(float4*)&C[off] = v;
            } else {
                float g = extra[row * 2 + gsel];
                float4 c = *(float4*)&C[off];
                c.x += g * v.x; c.y += g * v.y; c.z += g * v.z; c.w += g * v.w;
                *(float4*)&C[off] = c;
            }
        }
    }
}

// ---------------- flash-style causal attention (fp32) ----------------
// block = 128 threads = 128 query rows; K/V tiles of 64 keys in smem.
__global__ __launch_bounds__(128) void attn_k(const float* __restrict__ qkv,
                                              float* __restrict__ y)
{
    __shared__ float4 Ks[64][16];
    __shared__ float4 Vs[64][16];
    int qt = blockIdx.x, h = blockIdx.y, b = blockIdx.z;
    int tid = threadIdx.x;
    int q = qt * 128 + tid;

    const float4* qp = (const float4*)(qkv + (size_t)(b * TT + q) * C3 + h * HD);
    float4 qv[16], o[16];
    #pragma unroll
    for (int i = 0; i < 16; i++) { qv[i] = qp[i]; o[i] = make_float4(0.f, 0.f, 0.f, 0.f); }

    float m = -1e30f, l = 0.f;
    int nkt = 2 * qt + 2;   // covers keys up to qt*128+127

    for (int kt = 0; kt < nkt; kt++) {
        int k0 = kt * 64;
        __syncthreads();
        #pragma unroll
        for (int it = 0; it < 8; it++) {
            int idx = it * 128 + tid;
            int r = idx >> 4, c = idx & 15;
            size_t base = (size_t)(b * TT + k0 + r) * C3 + h * HD;
            Ks[r][c] = ((const float4*)(qkv + base + CDIM))[c];
            Vs[r][c] = ((const float4*)(qkv + base + 2 * CDIM))[c];
        }
        __syncthreads();

        #pragma unroll 1
        for (int jc = 0; jc < 64; jc += 16) {
            float s[16];
            #pragma unroll
            for (int jj = 0; jj < 16; jj++) {
                float a = 0.f;
                #pragma unroll
                for (int d = 0; d < 16; d++) {
                    float4 kk = Ks[jc + jj][d];
                    a += qv[d].x * kk.x + qv[d].y * kk.y + qv[d].z * kk.z + qv[d].w * kk.w;
                }
                s[jj] = (k0 + jc + jj <= q) ? a * 0.125f : -1e30f;
            }
            float mn = m;
            #pragma unroll
            for (int jj = 0; jj < 16; jj++) mn = fmaxf(mn, s[jj]);
            float corr = __expf(m - mn);
            l *= corr;
            #pragma unroll
            for (int d = 0; d < 16; d++) {
                o[d].x *= corr; o[d].y *= corr; o[d].z *= corr; o[d].w *= corr;
            }
            #pragma unroll
            for (int jj = 0; jj < 16; jj++) {
                float p = __expf(s[jj] - mn);
                l += p;
                #pragma unroll
                for (int d = 0; d < 16; d++) {
                    float4 vv = Vs[jc + jj][d];
                    o[d].x += p * vv.x; o[d].y += p * vv.y;
                    o[d].z += p * vv.z; o[d].w += p * vv.w;
                }
            }
            m = mn;
        }
    }
    float inv = 1.f / l;
    float4* yp = (float4*)(y + (size_t)(b * TT + q) * CDIM + h * HD);
    #pragma unroll
    for (int i = 0; i < 16; i++)
        yp[i] = make_float4(o[i].x * inv, o[i].y * inv, o[i].z * inv, o[i].w * inv);
}

// ---------------- MoE gating: one block of 128 threads per token ----------------
__global__ __launch_bounds__(128) void gate_k(const float* __restrict__ h2,
                                              const float* __restrict__ wg,
                                              float* __restrict__ gates,
                                              float* __restrict__ aux)
{
    int row = blockIdx.x, tid = threadIdx.x;
    const float* hp = h2 + (size_t)row * CDIM;
    float l0 = 0.f, l1 = 0.f;
    for (int i = tid; i < CDIM; i += 128) {
        float v = hp[i];
        l0 += v * wg[2 * i];
        l1 += v * wg[2 * i + 1];
    }
    #pragma unroll
    for (int o = 16; o; o >>= 1) {
        l0 += __shfl_down_sync(0xffffffffu, l0, o);
        l1 += __shfl_down_sync(0xffffffffu, l1, o);
    }
    __shared__ float s0[4], s1[4];
    if ((tid & 31) == 0) { s0[tid >> 5] = l0; s1[tid >> 5] = l1; }
    __syncthreads();
    if (tid == 0) {
        l0 = s0[0] + s0[1] + s0[2] + s0[3];
        l1 = s1[0] + s1[1] + s1[2] + s1[3];
        float mx = fmaxf(l0, l1);
        float e0 = __expf(l0 - mx), e1 = __expf(l1 - mx);
        float inv = 1.f / (e0 + e1);
        float g0 = e0 * inv, g1 = e1 * inv;   // raw softmax gates
        int bb = row >> 10;
        atomicAdd(&aux[bb * 2 + 0], g0);                       // density proxy sums
        atomicAdd(&aux[bb * 2 + 1], g1);
        atomicAdd(&aux[32 + bb * 2 + (g1 > g0 ? 1 : 0)], 1.f); // argmax counts (ties -> 0)
        float d = 1.f / (g0 + g1 + 1e-9f);
        gates[row * 2 + 0] = g0 * d;
        gates[row * 2 + 1] = g1 * d;
    }
}

__global__ void zero_k(float* aux) { aux[threadIdx.x] = 0.f; }

// aux = mean_{b,e}(density*proxy)*E*E = (4/32) * sum cnt*gsum / (1024*1024)
__global__ void aux_k(const float* __restrict__ aux, float* __restrict__ out)
{
    int tid = threadIdx.x;   // 32 threads
    float v = aux[tid] * aux[32 + tid];
    #pragma unroll
    for (int o = 16; o; o >>= 1) v += __shfl_down_sync(0xffffffffu, v, o);
    if (tid == 0) out[0] = v * (4.f / (32.f * 1024.f * 1024.f));
}

// ---------------- host orchestration ----------------
extern "C" void kernel_launch(void* const* d_in, const int* in_sizes, int n_in,
                              void* d_out, int out_size)
{
    const float* x     = (const float*)d_in[0];
    const float* ln1w  = (const float*)d_in[1];
    const float* ln1b  = (const float*)d_in[2];
    const float* wqkv  = (const float*)d_in[3];
    const float* bqkv  = (const float*)d_in[4];
    const float* wproj = (const float*)d_in[5];
    const float* bproj = (const float*)d_in[6];
    const float* ln2w  = (const float*)d_in[7];
    const float* ln2b  = (const float*)d_in[8];
    const float* wg    = (const float*)d_in[9];
    const float* w1    = (const float*)d_in[10];
    const float* w2    = (const float*)d_in[11];
    const float* w3    = (const float*)d_in[12];
    float* out = (float*)d_out;

    float *pln, *pqkv, *py, *ph1, *ph2, *pg, *paux;
    cudaGetSymbolAddress((void**)&pln,  g_ln);
    cudaGetSymbolAddress((void**)&pqkv, g_qkv);
    cudaGetSymbolAddress((void**)&py,   g_y);
    cudaGetSymbolAddress((void**)&ph1,  g_hid1);
    cudaGetSymbolAddress((void**)&ph2,  g_hid2);
    cudaGetSymbolAddress((void**)&pg,   g_gates);
    cudaGetSymbolAddress((void**)&paux, g_aux);

    // 1) LN1
    ln_k<<<BT, 256>>>(x, ln1w, ln1b, pln);
    // 2) QKV = ln1 @ wqkv + bqkv
    sgemm_k<0><<<dim3(C3 / 128, BT / 128), 256>>>(pln, wqkv, pqkv, bqkv, nullptr, BT, C3, CDIM, 0);
    // 3) causal attention
    attn_k<<<dim3(TT / 128, NHEAD, BB), 128>>>(pqkv, py);
    // 4) x_mid = x + y @ wproj + bproj  (written to d_out)
    sgemm_k<1><<<dim3(CDIM / 128, BT / 128), 256>>>(py, wproj, out, bproj, x, BT, CDIM, CDIM, 0);
    // 5) LN2 -> h2 (reuse g_ln)
    ln_k<<<BT, 256>>>(out, ln2w, ln2b, pln);
    // 6) gating + aux stats
    zero_k<<<1, 64>>>(paux);
    gate_k<<<BT, 128>>>(pln, wg, pg, paux);
    // 7) experts: dense — with E=2/top-2 every token hits both experts, no drops
    for (int e = 0; e < 2; e++) {
        sgemm_k<2><<<dim3(HID / 128, BT / 128), 256>>>(pln, w1 + (size_t)e * CDIM * HID, ph1,
                                                       nullptr, nullptr, BT, HID, CDIM, 0);
        sgemm_k<2><<<dim3(HID / 128, BT / 128), 256>>>(ph1, w2 + (size_t)e * HID * HID, ph2,
                                                       nullptr, nullptr, BT, HID, HID, 0);
        sgemm_k<3><<<dim3(CDIM / 128, BT / 128), 256>>>(ph2, w3 + (size_t)e * HID * CDIM, out,
                                                        nullptr, pg, BT, CDIM, HID, e);
    }
    // 8) aux loss scalar (last output element)
    aux_k<<<1, 32>>>(paux, out + (out_size - 1));
}

// round 17
// speedup vs baseline: 1.5983x; 1.5983x over previous
#include <cuda_runtime.h>
#include <cuda_bf16.h>
#include <cstdint>

// ---------------- problem constants ----------------
#define BB   16
#define TT   1024
#define CDIM 768
#define C3   2304      // 3*C
#define HID  3072      // 4*C
#define BT   16384     // B*T
#define NHEAD 12
#define HD   64

// ---------------- device scratch ----------------
__device__ float g_ln  [(size_t)BT * CDIM];   // ln1 out, then reused as h2
__device__ float g_qkv [(size_t)BT * C3];     // qkv
__device__ float g_y   [(size_t)BT * CDIM];   // attention out
__device__ float g_hid1[(size_t)BT * HID];
__device__ float g_hid2[(size_t)BT * HID];
__device__ float g_gates[(size_t)BT * 2];     // normalized combine gates
__device__ float g_aux [64];                  // [0..31]=gsum[b][e], [32..63]=cnt[b][e]

// ---------------- fused LayerNorm ----------------
__global__ __launch_bounds__(256) void ln_k(const float* __restrict__ x,
                                            const float* __restrict__ w,
                                            const float* __restrict__ b,
                                            float* __restrict__ out)
{
    __shared__ float sx[CDIM];
    __shared__ float red[8];
    __shared__ float stat[2];
    int row = blockIdx.x, tid = threadIdx.x;
    const float* xp = x + (size_t)row * CDIM;

    float s = 0.f;
    for (int i = tid; i < CDIM; i += 256) { float v = xp[i]; sx[i] = v; s += v; }
    #pragma unroll
    for (int o = 16; o; o >>= 1) s += __shfl_down_sync(0xffffffffu, s, o);
    if ((tid & 31) == 0) red[tid >> 5] = s;
    __syncthreads();
    if (tid == 0) {
        float t = 0.f;
        #pragma unroll
        for (int i = 0; i < 8; i++) t += red[i];
        stat[0] = t / (float)CDIM;
    }
    __syncthreads();
    float m = stat[0];
    float s2 = 0.f;
    for (int i = tid; i < CDIM; i += 256) { float d = sx[i] - m; s2 += d * d; }
    #pragma unroll
    for (int o = 16; o; o >>= 1) s2 += __shfl_down_sync(0xffffffffu, s2, o);
    if ((tid & 31) == 0) red[tid >> 5] = s2;
    __syncthreads();
    if (tid == 0) {
        float t = 0.f;
        #pragma unroll
        for (int i = 0; i < 8; i++) t += red[i];
        stat[1] = rsqrtf(t / (float)CDIM + 1e-5f);
    }
    __syncthreads();
    float r = stat[1];
    float* op = out + (size_t)row * CDIM;
    for (int i = tid; i < CDIM; i += 256) op[i] = (sx[i] - m) * r * w[i] + b[i];
}

// ---------------- split-bf16 tensor-core GEMM ----------------
// D = A(fp32) @ B(fp32), computed as Ah@Bh + Ah@Bl + Al@Bh (bf16 mma, fp32 accum).
// Block tile 128x128, BK=32, 256 threads = 8 warps (2x4), warp tile 64x32.
// EPI: 0 = C = acc + bias[n]
//      1 = C = acc + bias[n] + extra[row*N+n]     (residual write)
//      2 = C = leaky_relu(acc)
//      3 = C += extra[row*2+gsel] * acc           (gated MoE accumulate)

#define A_ST 40    // bf16 elements per A smem row (32 data + 8 pad) -> 80B stride
#define B_ST 136   // bf16 elements per B smem row (128 data + 8 pad) -> 272B stride

__device__ __forceinline__ uint32_t smem_u32(const void* p) {
    return (uint32_t)__cvta_generic_to_shared(p);
}

__device__ __forceinline__ void ldsm4(uint32_t* r, uint32_t addr) {
    asm volatile("ldmatrix.sync.aligned.m8n8.x4.shared.b16 {%0,%1,%2,%3},[%4];"
                 : "=r"(r[0]), "=r"(r[1]), "=r"(r[2]), "=r"(r[3]) : "r"(addr));
}
__device__ __forceinline__ void ldsm4t(uint32_t* r, uint32_t addr) {
    asm volatile("ldmatrix.sync.aligned.m8n8.x4.trans.shared.b16 {%0,%1,%2,%3},[%4];"
                 : "=r"(r[0]), "=r"(r[1]), "=r"(r[2]), "=r"(r[3]) : "r"(addr));
}
__device__ __forceinline__ void mma_bf16(float* c, const uint32_t* a,
                                         uint32_t b0, uint32_t b1) {
    asm volatile("mma.sync.aligned.m16n8k16.row.col.f32.bf16.bf16.f32 "
                 "{%0,%1,%2,%3},{%4,%5,%6,%7},{%8,%9},{%0,%1,%2,%3};"
                 : "+f"(c[0]), "+f"(c[1]), "+f"(c[2]), "+f"(c[3])
                 : "r"(a[0]), "r"(a[1]), "r"(a[2]), "r"(a[3]), "r"(b0), "r"(b1));
}

// split two floats into packed hi-bf16 pair and lo-bf16 pair (x in low half)
__device__ __forceinline__ void split_pair(float x, float y, uint32_t& hi, uint32_t& lo) {
    __nv_bfloat16 hx = __float2bfloat16(x);
    __nv_bfloat16 hy = __float2bfloat16(y);
    float rx = x - __bfloat162float(hx);
    float ry = y - __bfloat162float(hy);
    __nv_bfloat16 lx = __float2bfloat16(rx);
    __nv_bfloat16 ly = __float2bfloat16(ry);
    hi = (uint32_t)__bfloat16_as_ushort(hx) | ((uint32_t)__bfloat16_as_ushort(hy) << 16);
    lo = (uint32_t)__bfloat16_as_ushort(lx) | ((uint32_t)__bfloat16_as_ushort(ly) << 16);
}

template<int EPI>
__global__ __launch_bounds__(256, 1) void bgemm_k(const float* __restrict__ A,
                                                  const float* __restrict__ Bm,
                                                  float* __restrict__ C,
                                                  const float* __restrict__ bias,
                                                  const float* __restrict__ extra,
                                                  int M, int N, int K, int gsel)
{
    __shared__ __align__(16) uint16_t sAh[128 * A_ST];
    __shared__ __align__(16) uint16_t sAl[128 * A_ST];
    __shared__ __align__(16) uint16_t sBh[32 * B_ST];
    __shared__ __align__(16) uint16_t sBl[32 * B_ST];

    const int tid  = threadIdx.x;
    const int lane = tid & 31;
    const int warp = tid >> 5;
    const int wm = (warp >> 2) * 64;   // warp row offset within 128
    const int wn = (warp & 3) * 32;    // warp col offset within 128
    const int bx = blockIdx.x, by = blockIdx.y;

    // ldmatrix per-lane base addresses
    // A (non-trans): rows = wm + mt*16 + lane%16, k-half = lane/16
    const uint32_t aBaseH = smem_u32(sAh) + (uint32_t)(wm + (lane & 15)) * (A_ST * 2) + (lane >> 4) * 16;
    const uint32_t aBaseL = smem_u32(sAl) + (uint32_t)(wm + (lane & 15)) * (A_ST * 2) + (lane >> 4) * 16;
    // B (trans): k rows = ks*16 + lane%16, n = wn + p*16 + (lane/16)*8
    const uint32_t bBaseH = smem_u32(sBh) + (uint32_t)(lane & 15) * (B_ST * 2) + (uint32_t)wn * 2 + (lane >> 4) * 16;
    const uint32_t bBaseL = smem_u32(sBl) + (uint32_t)(lane & 15) * (B_ST * 2) + (uint32_t)wn * 2 + (lane >> 4) * 16;

    float acc[4][4][4];
    #pragma unroll
    for (int i = 0; i < 4; i++)
        #pragma unroll
        for (int j = 0; j < 4; j++)
            #pragma unroll
            for (int k = 0; k < 4; k++) acc[i][j][k] = 0.f;

    const int ntile = K >> 5;   // BK = 32
    float4 ra[4], rb[4];

    // first prefetch
    #pragma unroll
    for (int i = 0; i < 4; i++) {
        int idx = i * 256 + tid;
        ra[i] = *(const float4*)(A + (size_t)(by * 128 + (idx >> 3)) * K + (idx & 7) * 4);
        rb[i] = *(const float4*)(Bm + (size_t)(idx >> 5) * N + bx * 128 + (idx & 31) * 4);
    }

    for (int kt = 0; kt < ntile; kt++) {
        __syncthreads();
        // stage -> smem with bf16 split
        #pragma unroll
        for (int i = 0; i < 4; i++) {
            int idx = i * 256 + tid;
            int r = idx >> 3, kq = idx & 7;
            uint32_t h0, l0, h1, l1;
            split_pair(ra[i].x, ra[i].y, h0, l0);
            split_pair(ra[i].z, ra[i].w, h1, l1);
            *reinterpret_cast<uint2*>(&sAh[r * A_ST + kq * 4]) = make_uint2(h0, h1);
            *reinterpret_cast<uint2*>(&sAl[r * A_ST + kq * 4]) = make_uint2(l0, l1);
        }
        #pragma unroll
        for (int i = 0; i < 4; i++) {
            int idx = i * 256 + tid;
            int kr = idx >> 5, nq = idx & 31;
            uint32_t h0, l0, h1, l1;
            split_pair(rb[i].x, rb[i].y, h0, l0);
            split_pair(rb[i].z, rb[i].w, h1, l1);
            *reinterpret_cast<uint2*>(&sBh[kr * B_ST + nq * 4]) = make_uint2(h0, h1);
            *reinterpret_cast<uint2*>(&sBl[kr * B_ST + nq * 4]) = make_uint2(l0, l1);
        }
        __syncthreads();

        if (kt + 1 < ntile) {
            int k0 = (kt + 1) * 32;
            #pragma unroll
            for (int i = 0; i < 4; i++) {
                int idx = i * 256 + tid;
                ra[i] = *(const float4*)(A + (size_t)(by * 128 + (idx >> 3)) * K + k0 + (idx & 7) * 4);
                rb[i] = *(const float4*)(Bm + (size_t)(k0 + (idx >> 5)) * N + bx * 128 + (idx & 31) * 4);
            }
        }

        #pragma unroll
        for (int ks = 0; ks < 2; ks++) {
            uint32_t ah[4][4], al[4][4], bh[2][4], bl[2][4];
            #pragma unroll
            for (int mt = 0; mt < 4; mt++) {
                ldsm4(ah[mt], aBaseH + (uint32_t)mt * (16 * A_ST * 2) + ks * 32);
                ldsm4(al[mt], aBaseL + (uint32_t)mt * (16 * A_ST * 2) + ks * 32);
            }
            #pragma unroll
            for (int p = 0; p < 2; p++) {
                ldsm4t(bh[p], bBaseH + (uint32_t)ks * (16 * B_ST * 2) + p * 32);
                ldsm4t(bl[p], bBaseL + (uint32_t)ks * (16 * B_ST * 2) + p * 32);
            }
            // term hi*hi
            #pragma unroll
            for (int mt = 0; mt < 4; mt++)
                #pragma unroll
                for (int nt = 0; nt < 4; nt++)
                    mma_bf16(acc[mt][nt], ah[mt], bh[nt >> 1][(nt & 1) * 2], bh[nt >> 1][(nt & 1) * 2 + 1]);
            // term hi*lo
            #pragma unroll
            for (int mt = 0; mt < 4; mt++)
                #pragma unroll
                for (int nt = 0; nt < 4; nt++)
                    mma_bf16(acc[mt][nt], ah[mt], bl[nt >> 1][(nt & 1) * 2], bl[nt >> 1][(nt & 1) * 2 + 1]);
            // term lo*hi
            #pragma unroll
            for (int mt = 0; mt < 4; mt++)
                #pragma unroll
                for (int nt = 0; nt < 4; nt++)
                    mma_bf16(acc[mt][nt], al[mt], bh[nt >> 1][(nt & 1) * 2], bh[nt >> 1][(nt & 1) * 2 + 1]);
        }
    }

    // epilogue: c0,c1 at (row=lane/4, col=2*(lane%4)); c2,c3 at row+8
    #pragma unroll
    for (int mt = 0; mt < 4; mt++) {
        #pragma unroll
        for (int half = 0; half < 2; half++) {
            int row = by * 128 + wm + mt * 16 + (lane >> 2) + half * 8;
            #pragma unroll
            for (int nt = 0; nt < 4; nt++) {
                int col = bx * 128 + wn + nt * 8 + (lane & 3) * 2;
                float c0 = acc[mt][nt][half * 2 + 0];
                float c1 = acc[mt][nt][half * 2 + 1];
                size_t off = (size_t)row * N + col;
                if (EPI == 0) {
                    c0 += bias[col]; c1 += bias[col + 1];
                    *(float2*)&C[off] = make_float2(c0, c1);
                } else if (EPI == 1) {
                    float2 r2 = *(const float2*)&extra[off];
                    c0 += bias[col] + r2.x;
                    c1 += bias[col + 1] + r2.y;
                    *(float2*)&C[off] = make_float2(c0, c1);
                } else if (EPI == 2) {
                    c0 = c0 >= 0.f ? c0 : 0.01f * c0;
                    c1 = c1 >= 0.f ? c1 : 0.01f * c1;
                    *(float2*)&C[off] = make_float2(c0, c1);
                } else {
                    float g = extra[row * 2 + gsel];
                    float2 p = *(float2*)&C[off];
                    p.x += g * c0; p.y += g * c1;
                    *(float2*)&C[off] = p;
                }
            }
        }
    }
}

// ---------------- flash-style causal attention (fp32) ----------------
__global__ __launch_bounds__(128) void attn_k(const float* __restrict__ qkv,
                                              float* __restrict__ y)
{
    __shared__ float4 Ks[64][16];
    __shared__ float4 Vs[64][16];
    int qt = blockIdx.x, h = blockIdx.y, b = blockIdx.z;
    int tid = threadIdx.x;
    int q = qt * 128 + tid;

    const float4* qp = (const float4*)(qkv + (size_t)(b * TT + q) * C3 + h * HD);
    float4 qv[16], o[16];
    #pragma unroll
    for (int i = 0; i < 16; i++) { qv[i] = qp[i]; o[i] = make_float4(0.f, 0.f, 0.f, 0.f); }

    float m = -1e30f, l = 0.f;
    int nkt = 2 * qt + 2;

    for (int kt = 0; kt < nkt; kt++) {
        int k0 = kt * 64;
        __syncthreads();
        #pragma unroll
        for (int it = 0; it < 8; it++) {
            int idx = it * 128 + tid;
            int r = idx >> 4, c = idx & 15;
            size_t base = (size_t)(b * TT + k0 + r) * C3 + h * HD;
            Ks[r][c] = ((const float4*)(qkv + base + CDIM))[c];
            Vs[r][c] = ((const float4*)(qkv + base + 2 * CDIM))[c];
        }
        __syncthreads();

        #pragma unroll 1
        for (int jc = 0; jc < 64; jc += 16) {
            float s[16];
            #pragma unroll
            for (int jj = 0; jj < 16; jj++) {
                float a = 0.f;
                #pragma unroll
                for (int d = 0; d < 16; d++) {
                    float4 kk = Ks[jc + jj][d];
                    a += qv[d].x * kk.x + qv[d].y * kk.y + qv[d].z * kk.z + qv[d].w * kk.w;
                }
                s[jj] = (k0 + jc + jj <= q) ? a * 0.125f : -1e30f;
            }
            float mn = m;
            #pragma unroll
            for (int jj = 0; jj < 16; jj++) mn = fmaxf(mn, s[jj]);
            float corr = __expf(m - mn);
            l *= corr;
            #pragma unroll
            for (int d = 0; d < 16; d++) {
                o[d].x *= corr; o[d].y *= corr; o[d].z *= corr; o[d].w *= corr;
            }
            #pragma unroll
            for (int jj = 0; jj < 16; jj++) {
                float p = __expf(s[jj] - mn);
                l += p;
                #pragma unroll
                for (int d = 0; d < 16; d++) {
                    float4 vv = Vs[jc + jj][d];
                    o[d].x += p * vv.x; o[d].y += p * vv.y;
                    o[d].z += p * vv.z; o[d].w += p * vv.w;
                }
            }
            m = mn;
        }
    }
    float inv = 1.f / l;
    float4* yp = (float4*)(y + (size_t)(b * TT + q) * CDIM + h * HD);
    #pragma unroll
    for (int i = 0; i < 16; i++)
        yp[i] = make_float4(o[i].x * inv, o[i].y * inv, o[i].z * inv, o[i].w * inv);
}

// ---------------- MoE gating ----------------
__global__ __launch_bounds__(128) void gate_k(const float* __restrict__ h2,
                                              const float* __restrict__ wg,
                                              float* __restrict__ gates,
                                              float* __restrict__ aux)
{
    int row = blockIdx.x, tid = threadIdx.x;
    const float* hp = h2 + (size_t)row * CDIM;
    float l0 = 0.f, l1 = 0.f;
    for (int i = tid; i < CDIM; i += 128) {
        float v = hp[i];
        l0 += v * wg[2 * i];
        l1 += v * wg[2 * i + 1];
    }
    #pragma unroll
    for (int o = 16; o; o >>= 1) {
        l0 += __shfl_down_sync(0xffffffffu, l0, o);
        l1 += __shfl_down_sync(0xffffffffu, l1, o);
    }
    __shared__ float s0[4], s1[4];
    if ((tid & 31) == 0) { s0[tid >> 5] = l0; s1[tid >> 5] = l1; }
    __syncthreads();
    if (tid == 0) {
        l0 = s0[0] + s0[1] + s0[2] + s0[3];
        l1 = s1[0] + s1[1] + s1[2] + s1[3];
        float mx = fmaxf(l0, l1);
        float e0 = __expf(l0 - mx), e1 = __expf(l1 - mx);
        float inv = 1.f / (e0 + e1);
        float g0 = e0 * inv, g1 = e1 * inv;
        int bb = row >> 10;
        atomicAdd(&aux[bb * 2 + 0], g0);
        atomicAdd(&aux[bb * 2 + 1], g1);
        atomicAdd(&aux[32 + bb * 2 + (g1 > g0 ? 1 : 0)], 1.f);
        float d = 1.f / (g0 + g1 + 1e-9f);
        gates[row * 2 + 0] = g0 * d;
        gates[row * 2 + 1] = g1 * d;
    }
}

__global__ void zero_k(float* aux) { aux[threadIdx.x] = 0.f; }

__global__ void aux_k(const float* __restrict__ aux, float* __restrict__ out)
{
    int tid = threadIdx.x;
    float v = aux[tid] * aux[32 + tid];
    #pragma unroll
    for (int o = 16; o; o >>= 1) v += __shfl_down_sync(0xffffffffu, v, o);
    if (tid == 0) out[0] = v * (4.f / (32.f * 1024.f * 1024.f));
}

// ---------------- host orchestration ----------------
extern "C" void kernel_launch(void* const* d_in, const int* in_sizes, int n_in,
                              void* d_out, int out_size)
{
    const float* x     = (const float*)d_in[0];
    const float* ln1w  = (const float*)d_in[1];
    const float* ln1b  = (const float*)d_in[2];
    const float* wqkv  = (const float*)d_in[3];
    const float* bqkv  = (const float*)d_in[4];
    const float* wproj = (const float*)d_in[5];
    const float* bproj = (const float*)d_in[6];
    const float* ln2w  = (const float*)d_in[7];
    const float* ln2b  = (const float*)d_in[8];
    const float* wg    = (const float*)d_in[9];
    const float* w1    = (const float*)d_in[10];
    const float* w2    = (const float*)d_in[11];
    const float* w3    = (const float*)d_in[12];
    float* out = (float*)d_out;

    float *pln, *pqkv, *py, *ph1, *ph2, *pg, *paux;
    cudaGetSymbolAddress((void**)&pln,  g_ln);
    cudaGetSymbolAddress((void**)&pqkv, g_qkv);
    cudaGetSymbolAddress((void**)&py,   g_y);
    cudaGetSymbolAddress((void**)&ph1,  g_hid1);
    cudaGetSymbolAddress((void**)&ph2,  g_hid2);
    cudaGetSymbolAddress((void**)&pg,   g_gates);
    cudaGetSymbolAddress((void**)&paux, g_aux);

    // 1) LN1
    ln_k<<<BT, 256>>>(x, ln1w, ln1b, pln);
    // 2) QKV = ln1 @ wqkv + bqkv
    bgemm_k<0><<<dim3(C3 / 128, BT / 128), 256>>>(pln, wqkv, pqkv, bqkv, nullptr, BT, C3, CDIM, 0);
    // 3) causal attention
    attn_k<<<dim3(TT / 128, NHEAD, BB), 128>>>(pqkv, py);
    // 4) x_mid = x + y @ wproj + bproj  (written to d_out)
    bgemm_k<1><<<dim3(CDIM / 128, BT / 128), 256>>>(py, wproj, out, bproj, x, BT, CDIM, CDIM, 0);
    // 5) LN2 -> h2
    ln_k<<<BT, 256>>>(out, ln2w, ln2b, pln);
    // 6) gating + aux stats
    zero_k<<<1, 64>>>(paux);
    gate_k<<<BT, 128>>>(pln, wg, pg, paux);
    // 7) experts (dense: E=2/top-2 routes every token to both experts, no drops)
    for (int e = 0; e < 2; e++) {
        bgemm_k<2><<<dim3(HID / 128, BT / 128), 256>>>(pln, w1 + (size_t)e * CDIM * HID, ph1,
                                                       nullptr, nullptr, BT, HID, CDIM, 0);
        bgemm_k<2><<<dim3(HID / 128, BT / 128), 256>>>(ph1, w2 + (size_t)e * HID * HID, ph2,
                                                       nullptr, nullptr, BT, HID, HID, 0);
        bgemm_k<3><<<dim3(CDIM / 128, BT / 128), 256>>>(ph2, w3 + (size_t)e * HID * CDIM, out,
                                                        nullptr, pg, BT, CDIM, HID, e);
    }
    // 8) aux loss scalar
    aux_k<<<1, 32>>>(paux, out + (out_size - 1));
}